// round 6
// baseline (speedup 1.0000x reference)
#include <cuda_runtime.h>
#include <cstdint>
#include <math.h>

// Problem constants
constexpr int NB = 2;      // batch
constexpr int SL = 2048;   // sequence length
constexpr int DM = 1024;   // model dim
constexpr int NH = 16;     // heads
constexpr int DK = 64;     // head dim

// Tiling
constexpr int BM = 64;     // q rows per CTA
constexpr int BN = 64;     // keys per tile
constexpr int PAD = 4;
constexpr int STR = DK + PAD;   // 68 floats, keeps 16B alignment (68*4=272)

// Scratch for attention output [N, L, D]
__device__ float g_attn[NB * SL * DM];

// ---------------- helpers ----------------

__device__ __forceinline__ uint32_t f2tf(float x) {
    uint32_t u;
    asm("cvt.rna.tf32.f32 %0, %1;" : "=r"(u) : "f"(x));
    return u;
}

__device__ __forceinline__ void split2(float x, float& hi, float& lo) {
    hi = __uint_as_float(f2tf(x));
    lo = __uint_as_float(f2tf(x - hi));
}

__device__ __forceinline__ void split_store4(float4 v, float* hp, float* lp) {
    float h0, l0, h1, l1, h2, l2, h3, l3;
    split2(v.x, h0, l0); split2(v.y, h1, l1);
    split2(v.z, h2, l2); split2(v.w, h3, l3);
    *reinterpret_cast<float4*>(hp) = make_float4(h0, h1, h2, h3);
    *reinterpret_cast<float4*>(lp) = make_float4(l0, l1, l2, l3);
}

// m16n8k8 tf32 mma: C += A * B  (A row-major 16x8, B col-major 8x8)
__device__ __forceinline__ void mma8(float* c, const uint32_t a[4], uint32_t b0, uint32_t b1) {
    asm volatile(
        "mma.sync.aligned.m16n8k8.row.col.f32.tf32.tf32.f32 "
        "{%0,%1,%2,%3},{%4,%5,%6,%7},{%8,%9},{%0,%1,%2,%3};\n"
        : "+f"(c[0]), "+f"(c[1]), "+f"(c[2]), "+f"(c[3])
        : "r"(a[0]), "r"(a[1]), "r"(a[2]), "r"(a[3]), "r"(b0), "r"(b1));
}

// ---------------- attention kernel ----------------
// grid: (SL/BM, NH, NB), block: 128 threads (4 warps, 16 q-rows each)

constexpr int ATTN_SMEM = 6 * BM * STR * 4;   // Qh,Ql,Kh(=Ph),Kl(=Pl),Vh,Vl

__global__ void __launch_bounds__(128, 2)
attn_kernel(const float* __restrict__ Q, const float* __restrict__ K,
            const float* __restrict__ V) {
    extern __shared__ float sm[];
    float* sQh = sm;
    float* sQl = sQh + BM * STR;
    float* sKh = sQl + BM * STR;   // aliased with P hi
    float* sKl = sKh + BM * STR;   // aliased with P lo
    float* sVh = sKl + BM * STR;
    float* sVl = sVh + BM * STR;

    const int tid  = threadIdx.x;
    const int lane = tid & 31;
    const int warp = tid >> 5;
    const int grp  = lane >> 2;   // 0..7
    const int tq   = lane & 3;    // 0..3
    const int wr0  = warp * 16;

    const int n  = blockIdx.z;
    const int h  = blockIdx.y;
    const int q0 = blockIdx.x * BM;
    const int hcol = h * DK;

    // Load Q tile (64 rows x 64 cols) -> hi/lo smem
    #pragma unroll
    for (int j = tid; j < BM * 16; j += 128) {
        int r = j >> 4, c4 = (j & 15) * 4;
        float4 v4 = *reinterpret_cast<const float4*>(
            Q + (size_t)(n * SL + q0 + r) * DM + hcol + c4);
        split_store4(v4, &sQh[r * STR + c4], &sQl[r * STR + c4]);
    }

    float o[8][4];
    #pragma unroll
    for (int nt = 0; nt < 8; ++nt)
        #pragma unroll
        for (int i = 0; i < 4; ++i) o[nt][i] = 0.f;

    float mA = -INFINITY, mB = -INFINITY, lA = 0.f, lB = 0.f;

    for (int kt = 0; kt < SL / BN; ++kt) {
        __syncthreads();   // prior PV done; safe to overwrite K(=P), V
        const int k0 = kt * BN;

        // Load K and V tiles
        #pragma unroll
        for (int j = tid; j < BN * 16; j += 128) {
            int r = j >> 4, c4 = (j & 15) * 4;
            size_t g = (size_t)(n * SL + k0 + r) * DM + hcol + c4;
            float4 kv = *reinterpret_cast<const float4*>(K + g);
            split_store4(kv, &sKh[r * STR + c4], &sKl[r * STR + c4]);
            float4 vv = *reinterpret_cast<const float4*>(V + g);
            split_store4(vv, &sVh[r * STR + c4], &sVl[r * STR + c4]);
        }
        __syncthreads();

        // S = Q K^T  (per warp: 16 x 64), 3-term tf32 split
        float c[8][4];
        #pragma unroll
        for (int nt = 0; nt < 8; ++nt)
            #pragma unroll
            for (int i = 0; i < 4; ++i) c[nt][i] = 0.f;

        #pragma unroll
        for (int kc = 0; kc < 8; ++kc) {
            const int a0 = (wr0 + grp) * STR + kc * 8 + tq;
            const int a1 = (wr0 + grp + 8) * STR + kc * 8 + tq;
            uint32_t ah[4] = {__float_as_uint(sQh[a0]), __float_as_uint(sQh[a1]),
                              __float_as_uint(sQh[a0 + 4]), __float_as_uint(sQh[a1 + 4])};
            uint32_t al[4] = {__float_as_uint(sQl[a0]), __float_as_uint(sQl[a1]),
                              __float_as_uint(sQl[a0 + 4]), __float_as_uint(sQl[a1 + 4])};
            #pragma unroll
            for (int nt = 0; nt < 8; ++nt) {
                const int br = (nt * 8 + grp) * STR + kc * 8 + tq;
                uint32_t bh0 = __float_as_uint(sKh[br]);
                uint32_t bh1 = __float_as_uint(sKh[br + 4]);
                uint32_t bl0 = __float_as_uint(sKl[br]);
                uint32_t bl1 = __float_as_uint(sKl[br + 4]);
                mma8(c[nt], ah, bh0, bh1);
                mma8(c[nt], ah, bl0, bl1);
                mma8(c[nt], al, bh0, bh1);
            }
        }
        __syncthreads();   // all warps done reading K before P overwrite

        // Online softmax (rows rA=wr0+grp, rB=wr0+grp+8)
        float rmA = -INFINITY, rmB = -INFINITY;
        #pragma unroll
        for (int nt = 0; nt < 8; ++nt) {
            c[nt][0] *= 0.125f; c[nt][1] *= 0.125f;
            c[nt][2] *= 0.125f; c[nt][3] *= 0.125f;
            rmA = fmaxf(rmA, fmaxf(c[nt][0], c[nt][1]));
            rmB = fmaxf(rmB, fmaxf(c[nt][2], c[nt][3]));
        }
        rmA = fmaxf(rmA, __shfl_xor_sync(0xffffffffu, rmA, 1));
        rmA = fmaxf(rmA, __shfl_xor_sync(0xffffffffu, rmA, 2));
        rmB = fmaxf(rmB, __shfl_xor_sync(0xffffffffu, rmB, 1));
        rmB = fmaxf(rmB, __shfl_xor_sync(0xffffffffu, rmB, 2));

        const float mnA = fmaxf(mA, rmA), mnB = fmaxf(mB, rmB);
        const float corrA = __expf(mA - mnA), corrB = __expf(mB - mnB);

        float sA = 0.f, sB = 0.f;
        #pragma unroll
        for (int nt = 0; nt < 8; ++nt) {
            float p0 = __expf(c[nt][0] - mnA);
            float p1 = __expf(c[nt][1] - mnA);
            float p2 = __expf(c[nt][2] - mnB);
            float p3 = __expf(c[nt][3] - mnB);
            sA += p0 + p1; sB += p2 + p3;
            float h0, l0, h1, l1, h2, l2, h3, l3;
            split2(p0, h0, l0); split2(p1, h1, l1);
            split2(p2, h2, l2); split2(p3, h3, l3);
            const int pr0 = (wr0 + grp) * STR + nt * 8 + tq * 2;
            const int pr1 = (wr0 + grp + 8) * STR + nt * 8 + tq * 2;
            sKh[pr0] = h0; sKh[pr0 + 1] = h1;
            sKl[pr0] = l0; sKl[pr0 + 1] = l1;
            sKh[pr1] = h2; sKh[pr1 + 1] = h3;
            sKl[pr1] = l2; sKl[pr1 + 1] = l3;
        }
        sA += __shfl_xor_sync(0xffffffffu, sA, 1);
        sA += __shfl_xor_sync(0xffffffffu, sA, 2);
        sB += __shfl_xor_sync(0xffffffffu, sB, 1);
        sB += __shfl_xor_sync(0xffffffffu, sB, 2);

        lA = lA * corrA + sA;
        lB = lB * corrB + sB;
        mA = mnA; mB = mnB;

        #pragma unroll
        for (int nt = 0; nt < 8; ++nt) {
            o[nt][0] *= corrA; o[nt][1] *= corrA;
            o[nt][2] *= corrB; o[nt][3] *= corrB;
        }
        __syncwarp();   // each warp reads only its own P rows

        // O += P V   (contract over key index)
        #pragma unroll
        for (int kc = 0; kc < 8; ++kc) {
            const int a0 = (wr0 + grp) * STR + kc * 8 + tq;
            const int a1 = (wr0 + grp + 8) * STR + kc * 8 + tq;
            uint32_t ah[4] = {__float_as_uint(sKh[a0]), __float_as_uint(sKh[a1]),
                              __float_as_uint(sKh[a0 + 4]), __float_as_uint(sKh[a1 + 4])};
            uint32_t al[4] = {__float_as_uint(sKl[a0]), __float_as_uint(sKl[a1]),
                              __float_as_uint(sKl[a0 + 4]), __float_as_uint(sKl[a1 + 4])};
            #pragma unroll
            for (int nt = 0; nt < 8; ++nt) {
                const int b0i = (kc * 8 + tq) * STR + nt * 8 + grp;
                const int b1i = (kc * 8 + tq + 4) * STR + nt * 8 + grp;
                uint32_t bh0 = __float_as_uint(sVh[b0i]);
                uint32_t bh1 = __float_as_uint(sVh[b1i]);
                uint32_t bl0 = __float_as_uint(sVl[b0i]);
                uint32_t bl1 = __float_as_uint(sVl[b1i]);
                mma8(o[nt], ah, bh0, bh1);
                mma8(o[nt], ah, bl0, bl1);
                mma8(o[nt], al, bh0, bh1);
            }
        }
    }

    // Epilogue: normalize and write to scratch
    const float invA = 1.f / lA, invB = 1.f / lB;
    #pragma unroll
    for (int nt = 0; nt < 8; ++nt) {
        const int col = hcol + nt * 8 + tq * 2;
        size_t r0 = (size_t)(n * SL + q0 + wr0 + grp) * DM + col;
        size_t r1 = (size_t)(n * SL + q0 + wr0 + grp + 8) * DM + col;
        g_attn[r0]     = o[nt][0] * invA;
        g_attn[r0 + 1] = o[nt][1] * invA;
        g_attn[r1]     = o[nt][2] * invB;
        g_attn[r1 + 1] = o[nt][3] * invB;
    }
}

// ---------------- fc_out GEMM: out = attn @ W^T + b ----------------
// grid: (DM/64, N*SL/64), block: 128 threads

constexpr int FC_SMEM = 4 * 64 * STR * 4;

__global__ void __launch_bounds__(128, 2)
fc_kernel(const float* __restrict__ W, const float* __restrict__ bias,
          float* __restrict__ out) {
    extern __shared__ float sm[];
    float* sAh = sm;
    float* sAl = sAh + 64 * STR;
    float* sWh = sAl + 64 * STR;
    float* sWl = sWh + 64 * STR;

    const int tid  = threadIdx.x;
    const int lane = tid & 31;
    const int warp = tid >> 5;
    const int grp  = lane >> 2;
    const int tq   = lane & 3;
    const int wr0  = warp * 16;

    const int m0 = blockIdx.y * 64;
    const int n0 = blockIdx.x * 64;

    float c[8][4];
    #pragma unroll
    for (int nt = 0; nt < 8; ++nt)
        #pragma unroll
        for (int i = 0; i < 4; ++i) c[nt][i] = 0.f;

    for (int kt = 0; kt < DM / 64; ++kt) {
        __syncthreads();
        const int k0 = kt * 64;
        #pragma unroll
        for (int j = tid; j < 64 * 16; j += 128) {
            int r = j >> 4, c4 = (j & 15) * 4;
            float4 a4 = *reinterpret_cast<const float4*>(
                g_attn + (size_t)(m0 + r) * DM + k0 + c4);
            split_store4(a4, &sAh[r * STR + c4], &sAl[r * STR + c4]);
            float4 w4 = *reinterpret_cast<const float4*>(
                W + (size_t)(n0 + r) * DM + k0 + c4);
            split_store4(w4, &sWh[r * STR + c4], &sWl[r * STR + c4]);
        }
        __syncthreads();

        #pragma unroll
        for (int kc = 0; kc < 8; ++kc) {
            const int a0 = (wr0 + grp) * STR + kc * 8 + tq;
            const int a1 = (wr0 + grp + 8) * STR + kc * 8 + tq;
            uint32_t ah[4] = {__float_as_uint(sAh[a0]), __float_as_uint(sAh[a1]),
                              __float_as_uint(sAh[a0 + 4]), __float_as_uint(sAh[a1 + 4])};
            uint32_t al[4] = {__float_as_uint(sAl[a0]), __float_as_uint(sAl[a1]),
                              __float_as_uint(sAl[a0 + 4]), __float_as_uint(sAl[a1 + 4])};
            #pragma unroll
            for (int nt = 0; nt < 8; ++nt) {
                const int br = (nt * 8 + grp) * STR + kc * 8 + tq;
                uint32_t bh0 = __float_as_uint(sWh[br]);
                uint32_t bh1 = __float_as_uint(sWh[br + 4]);
                uint32_t bl0 = __float_as_uint(sWl[br]);
                uint32_t bl1 = __float_as_uint(sWl[br + 4]);
                mma8(c[nt], ah, bh0, bh1);
                mma8(c[nt], ah, bl0, bl1);
                mma8(c[nt], al, bh0, bh1);
            }
        }
    }

    // Epilogue: bias + store
    #pragma unroll
    for (int nt = 0; nt < 8; ++nt) {
        const int col = n0 + nt * 8 + tq * 2;
        const float b0 = bias[col], b1 = bias[col + 1];
        const size_t r0 = (size_t)(m0 + wr0 + grp) * DM + col;
        const size_t r1 = (size_t)(m0 + wr0 + grp + 8) * DM + col;
        out[r0]     = c[nt][0] + b0;
        out[r0 + 1] = c[nt][1] + b1;
        out[r1]     = c[nt][2] + b0;
        out[r1 + 1] = c[nt][3] + b1;
    }
}

// ---------------- launch ----------------

extern "C" void kernel_launch(void* const* d_in, const int* in_sizes, int n_in,
                              void* d_out, int out_size) {
    const float* values  = (const float*)d_in[0];
    const float* keys    = (const float*)d_in[1];
    const float* queries = (const float*)d_in[2];
    const float* fc_w    = (const float*)d_in[3];
    const float* fc_b    = (const float*)d_in[4];
    float* out = (float*)d_out;

    cudaFuncSetAttribute(attn_kernel, cudaFuncAttributeMaxDynamicSharedMemorySize, ATTN_SMEM);
    cudaFuncSetAttribute(fc_kernel, cudaFuncAttributeMaxDynamicSharedMemorySize, FC_SMEM);

    attn_kernel<<<dim3(SL / BM, NH, NB), 128, ATTN_SMEM>>>(queries, keys, values);
    fc_kernel<<<dim3(DM / 64, (NB * SL) / 64), 128, FC_SMEM>>>(fc_w, fc_b, out);
}

// round 7
// speedup vs baseline: 1.8957x; 1.8957x over previous
#include <cuda_runtime.h>
#include <cuda_bf16.h>
#include <cstdint>
#include <math.h>

// Problem constants
constexpr int NB = 2;      // batch
constexpr int SL = 2048;   // sequence length
constexpr int DM = 1024;   // model dim
constexpr int NH = 16;     // heads
constexpr int DK = 64;     // head dim

constexpr int BM = 64;     // q rows per CTA
constexpr int BN = 64;     // keys per tile
constexpr int STRB = 72;   // bf16 elems per smem row (144B: 16B aligned, LDSM conflict-free)

// ---------- device scratch (bf16 hi/lo splits) ----------
__device__ __nv_bfloat16 g_qh[NB * SL * DM];
__device__ __nv_bfloat16 g_ql[NB * SL * DM];
__device__ __nv_bfloat16 g_kh[NB * SL * DM];
__device__ __nv_bfloat16 g_kl[NB * SL * DM];
__device__ __nv_bfloat16 g_vh[NB * SL * DM];
__device__ __nv_bfloat16 g_vl[NB * SL * DM];
__device__ __nv_bfloat16 g_ah[NB * SL * DM];   // attention output hi
__device__ __nv_bfloat16 g_al[NB * SL * DM];   // attention output lo
__device__ __nv_bfloat16 g_wh[DM * DM];
__device__ __nv_bfloat16 g_wl[DM * DM];

// ---------------- helpers ----------------

__device__ __forceinline__ uint32_t pack2(float e0, float e1) {
    // packed bf16x2: low half = e0, high half = e1
    uint32_t r;
    asm("cvt.rn.bf16x2.f32 %0, %1, %2;" : "=r"(r) : "f"(e1), "f"(e0));
    return r;
}

__device__ __forceinline__ float bfhi(float x) {
    return __bfloat162float(__float2bfloat16(x));
}

__device__ __forceinline__ void split_pack4(float4 v, uint2& hi, uint2& lo) {
    float h0 = bfhi(v.x), h1 = bfhi(v.y), h2 = bfhi(v.z), h3 = bfhi(v.w);
    hi.x = pack2(h0, h1);            hi.y = pack2(h2, h3);
    lo.x = pack2(v.x - h0, v.y - h1); lo.y = pack2(v.z - h2, v.w - h3);
}

__device__ __forceinline__ void ldsm4(uint32_t r[4], const __nv_bfloat16* p) {
    uint32_t a = (uint32_t)__cvta_generic_to_shared(p);
    asm volatile("ldmatrix.sync.aligned.m8n8.x4.shared.b16 {%0,%1,%2,%3},[%4];"
                 : "=r"(r[0]), "=r"(r[1]), "=r"(r[2]), "=r"(r[3]) : "r"(a));
}

__device__ __forceinline__ void ldsm4t(uint32_t r[4], const __nv_bfloat16* p) {
    uint32_t a = (uint32_t)__cvta_generic_to_shared(p);
    asm volatile("ldmatrix.sync.aligned.m8n8.x4.trans.shared.b16 {%0,%1,%2,%3},[%4];"
                 : "=r"(r[0]), "=r"(r[1]), "=r"(r[2]), "=r"(r[3]) : "r"(a));
}

// m16n8k16 bf16 mma: C += A*B  (A row-major 16x16, B col-major 16x8)
__device__ __forceinline__ void mma16(float* c, const uint32_t a[4], uint32_t b0, uint32_t b1) {
    asm volatile(
        "mma.sync.aligned.m16n8k16.row.col.f32.bf16.bf16.f32 "
        "{%0,%1,%2,%3},{%4,%5,%6,%7},{%8,%9},{%0,%1,%2,%3};\n"
        : "+f"(c[0]), "+f"(c[1]), "+f"(c[2]), "+f"(c[3])
        : "r"(a[0]), "r"(a[1]), "r"(a[2]), "r"(a[3]), "r"(b0), "r"(b1));
}

__device__ __forceinline__ float fexp2(float x) {
    float y;
    asm("ex2.approx.f32 %0, %1;" : "=f"(y) : "f"(x));
    return y;
}

// ---------------- split kernels (run once per launch) ----------------

__device__ __forceinline__ void split_store(const float4* src, int i,
                                            __nv_bfloat16* hi, __nv_bfloat16* lo) {
    float4 v = src[i];
    uint2 h, l;
    split_pack4(v, h, l);
    reinterpret_cast<uint2*>(hi)[i] = h;
    reinterpret_cast<uint2*>(lo)[i] = l;
}

__global__ void split_q(const float4* __restrict__ s) {
    int i = blockIdx.x * 256 + threadIdx.x;
    split_store(s, i, g_qh, g_ql);
}
__global__ void split_k(const float4* __restrict__ s) {
    int i = blockIdx.x * 256 + threadIdx.x;
    split_store(s, i, g_kh, g_kl);
}
__global__ void split_v(const float4* __restrict__ s) {
    int i = blockIdx.x * 256 + threadIdx.x;
    split_store(s, i, g_vh, g_vl);
}
__global__ void split_w(const float4* __restrict__ s) {
    int i = blockIdx.x * 256 + threadIdx.x;
    split_store(s, i, g_wh, g_wl);
}

// ---------------- attention kernel ----------------
// grid: (SL/BM, NH, NB), block: 128 threads (4 warps, 16 q-rows each)

constexpr int ATTN_SMEM = 6 * BM * STRB * 2;   // Qh,Ql,Kh,Kl,Vh,Vl bf16 = 55296 B

__global__ void __launch_bounds__(128, 2)
attn_kernel() {
    extern __shared__ __nv_bfloat16 sm[];
    __nv_bfloat16* sQh = sm;
    __nv_bfloat16* sQl = sQh + BM * STRB;
    __nv_bfloat16* sKh = sQl + BM * STRB;
    __nv_bfloat16* sKl = sKh + BN * STRB;
    __nv_bfloat16* sVh = sKl + BN * STRB;
    __nv_bfloat16* sVl = sVh + BN * STRB;

    const int tid  = threadIdx.x;
    const int lane = tid & 31;
    const int warp = tid >> 5;
    const int grp  = lane >> 2;
    const int tq   = lane & 3;
    const int wr0  = warp * 16;

    const int n  = blockIdx.z;
    const int h  = blockIdx.y;
    const int q0 = blockIdx.x * BM;
    const int hcol = h * DK;

    // ldmatrix lane->address mappings
    const int rowsel = lane & 15;        // non-trans: local row
    const int cb8    = (lane >> 4) * 8;  // non-trans: col half
    const int keyr   = (lane & 7) + ((lane >> 3) & 1) * 8;  // trans: key row
    const int dh8    = (lane >> 4) * 8;                     // trans: d half

    // Load Q tile (pure bf16 copy)
    #pragma unroll
    for (int j = tid; j < BM * 8; j += 128) {
        int r = j >> 3, cc = (j & 7) * 8;
        size_t g = (size_t)(n * SL + q0 + r) * DM + hcol + cc;
        *reinterpret_cast<uint4*>(sQh + r * STRB + cc) = *reinterpret_cast<const uint4*>(g_qh + g);
        *reinterpret_cast<uint4*>(sQl + r * STRB + cc) = *reinterpret_cast<const uint4*>(g_ql + g);
    }
    __syncthreads();

    // Preload Q A-fragments for the whole kt loop
    uint32_t qh[4][4], ql[4][4];
    #pragma unroll
    for (int kb = 0; kb < 4; ++kb) {
        const int off = (wr0 + rowsel) * STRB + kb * 16 + cb8;
        ldsm4(qh[kb], sQh + off);
        ldsm4(ql[kb], sQl + off);
    }

    float o[8][4];
    #pragma unroll
    for (int nt = 0; nt < 8; ++nt)
        #pragma unroll
        for (int i = 0; i < 4; ++i) o[nt][i] = 0.f;

    float mA = -INFINITY, mB = -INFINITY, lA = 0.f, lB = 0.f;

    for (int kt = 0; kt < SL / BN; ++kt) {
        __syncthreads();   // previous tile fully consumed
        const int k0 = kt * BN;

        #pragma unroll
        for (int j = tid; j < BN * 8; j += 128) {
            int r = j >> 3, cc = (j & 7) * 8;
            size_t g = (size_t)(n * SL + k0 + r) * DM + hcol + cc;
            *reinterpret_cast<uint4*>(sKh + r * STRB + cc) = *reinterpret_cast<const uint4*>(g_kh + g);
            *reinterpret_cast<uint4*>(sKl + r * STRB + cc) = *reinterpret_cast<const uint4*>(g_kl + g);
            *reinterpret_cast<uint4*>(sVh + r * STRB + cc) = *reinterpret_cast<const uint4*>(g_vh + g);
            *reinterpret_cast<uint4*>(sVl + r * STRB + cc) = *reinterpret_cast<const uint4*>(g_vl + g);
        }
        __syncthreads();

        // ---- S = Q K^T, 3-pass bf16 split ----
        float c[8][4];
        #pragma unroll
        for (int nt = 0; nt < 8; ++nt)
            #pragma unroll
            for (int i = 0; i < 4; ++i) c[nt][i] = 0.f;

        #pragma unroll
        for (int kb = 0; kb < 4; ++kb) {
            #pragma unroll
            for (int np = 0; np < 4; ++np) {
                uint32_t kh[4], kl2[4];
                const int off = (np * 16 + rowsel) * STRB + kb * 16 + cb8;
                ldsm4(kh,  sKh + off);
                ldsm4(kl2, sKl + off);
                mma16(c[2 * np],     qh[kb], kh[0],  kh[2]);
                mma16(c[2 * np],     qh[kb], kl2[0], kl2[2]);
                mma16(c[2 * np],     ql[kb], kh[0],  kh[2]);
                mma16(c[2 * np + 1], qh[kb], kh[1],  kh[3]);
                mma16(c[2 * np + 1], qh[kb], kl2[1], kl2[3]);
                mma16(c[2 * np + 1], ql[kb], kh[1],  kh[3]);
            }
        }

        // ---- online softmax (base-2 domain; scale = 1/8 * log2 e) ----
        constexpr float SC = 0.125f * 1.44269504088896f;
        float rmA = -INFINITY, rmB = -INFINITY;
        #pragma unroll
        for (int nt = 0; nt < 8; ++nt) {
            c[nt][0] *= SC; c[nt][1] *= SC; c[nt][2] *= SC; c[nt][3] *= SC;
            rmA = fmaxf(rmA, fmaxf(c[nt][0], c[nt][1]));
            rmB = fmaxf(rmB, fmaxf(c[nt][2], c[nt][3]));
        }
        rmA = fmaxf(rmA, __shfl_xor_sync(0xffffffffu, rmA, 1));
        rmA = fmaxf(rmA, __shfl_xor_sync(0xffffffffu, rmA, 2));
        rmB = fmaxf(rmB, __shfl_xor_sync(0xffffffffu, rmB, 1));
        rmB = fmaxf(rmB, __shfl_xor_sync(0xffffffffu, rmB, 2));

        const float mnA = fmaxf(mA, rmA), mnB = fmaxf(mB, rmB);
        const float corrA = fexp2(mA - mnA), corrB = fexp2(mB - mnB);

        float sA = 0.f, sB = 0.f;
        #pragma unroll
        for (int nt = 0; nt < 8; ++nt) {
            c[nt][0] = fexp2(c[nt][0] - mnA);
            c[nt][1] = fexp2(c[nt][1] - mnA);
            c[nt][2] = fexp2(c[nt][2] - mnB);
            c[nt][3] = fexp2(c[nt][3] - mnB);
            sA += c[nt][0] + c[nt][1];
            sB += c[nt][2] + c[nt][3];
        }
        sA += __shfl_xor_sync(0xffffffffu, sA, 1);
        sA += __shfl_xor_sync(0xffffffffu, sA, 2);
        sB += __shfl_xor_sync(0xffffffffu, sB, 1);
        sB += __shfl_xor_sync(0xffffffffu, sB, 2);

        lA = lA * corrA + sA;
        lB = lB * corrB + sB;
        mA = mnA; mB = mnB;

        #pragma unroll
        for (int nt = 0; nt < 8; ++nt) {
            o[nt][0] *= corrA; o[nt][1] *= corrA;
            o[nt][2] *= corrB; o[nt][3] *= corrB;
        }

        // ---- build P A-fragments in registers (C frag of QK == A frag of PV) ----
        uint32_t ph[4][4], pl[4][4];
        #pragma unroll
        for (int j2 = 0; j2 < 4; ++j2) {
            const float p00 = c[2 * j2][0],     p01 = c[2 * j2][1];
            const float p02 = c[2 * j2][2],     p03 = c[2 * j2][3];
            const float p10 = c[2 * j2 + 1][0], p11 = c[2 * j2 + 1][1];
            const float p12 = c[2 * j2 + 1][2], p13 = c[2 * j2 + 1][3];
            const float h00 = bfhi(p00), h01 = bfhi(p01), h02 = bfhi(p02), h03 = bfhi(p03);
            const float h10 = bfhi(p10), h11 = bfhi(p11), h12 = bfhi(p12), h13 = bfhi(p13);
            ph[j2][0] = pack2(h00, h01);  pl[j2][0] = pack2(p00 - h00, p01 - h01);
            ph[j2][1] = pack2(h02, h03);  pl[j2][1] = pack2(p02 - h02, p03 - h03);
            ph[j2][2] = pack2(h10, h11);  pl[j2][2] = pack2(p10 - h10, p11 - h11);
            ph[j2][3] = pack2(h12, h13);  pl[j2][3] = pack2(p12 - h12, p13 - h13);
        }

        // ---- O += P V (V fragments via ldmatrix.trans) ----
        #pragma unroll
        for (int j2 = 0; j2 < 4; ++j2) {
            #pragma unroll
            for (int np = 0; np < 4; ++np) {
                uint32_t vh[4], vl[4];
                const int off = (j2 * 16 + keyr) * STRB + np * 16 + dh8;
                ldsm4t(vh, sVh + off);
                ldsm4t(vl, sVl + off);
                mma16(o[2 * np],     ph[j2], vh[0], vh[1]);
                mma16(o[2 * np],     ph[j2], vl[0], vl[1]);
                mma16(o[2 * np],     pl[j2], vh[0], vh[1]);
                mma16(o[2 * np + 1], ph[j2], vh[2], vh[3]);
                mma16(o[2 * np + 1], ph[j2], vl[2], vl[3]);
                mma16(o[2 * np + 1], pl[j2], vh[2], vh[3]);
            }
        }
    }

    // ---- epilogue: normalize, split to bf16 hi/lo scratch ----
    const float invA = 1.f / lA, invB = 1.f / lB;
    #pragma unroll
    for (int nt = 0; nt < 8; ++nt) {
        const int col = hcol + nt * 8 + tq * 2;
        const size_t r0 = (size_t)(n * SL + q0 + wr0 + grp) * DM + col;
        const size_t r1 = (size_t)(n * SL + q0 + wr0 + grp + 8) * DM + col;
        const float i0 = o[nt][0] * invA, i1 = o[nt][1] * invA;
        const float i2 = o[nt][2] * invB, i3 = o[nt][3] * invB;
        const float h0 = bfhi(i0), h1 = bfhi(i1), h2 = bfhi(i2), h3 = bfhi(i3);
        *reinterpret_cast<uint32_t*>(g_ah + r0) = pack2(h0, h1);
        *reinterpret_cast<uint32_t*>(g_al + r0) = pack2(i0 - h0, i1 - h1);
        *reinterpret_cast<uint32_t*>(g_ah + r1) = pack2(h2, h3);
        *reinterpret_cast<uint32_t*>(g_al + r1) = pack2(i2 - h2, i3 - h3);
    }
}

// ---------------- fc_out GEMM: out = attn @ W^T + b ----------------
// grid: (DM/64, N*SL/64), block: 128 threads

constexpr int FC_SMEM = 4 * 64 * STRB * 2;   // Ah,Al,Wh,Wl = 36864 B

__global__ void __launch_bounds__(128, 2)
fc_kernel(const float* __restrict__ bias, float* __restrict__ out) {
    extern __shared__ __nv_bfloat16 fsm[];
    __nv_bfloat16* sAh = fsm;
    __nv_bfloat16* sAl = sAh + 64 * STRB;
    __nv_bfloat16* sWh = sAl + 64 * STRB;
    __nv_bfloat16* sWl = sWh + 64 * STRB;

    const int tid  = threadIdx.x;
    const int lane = tid & 31;
    const int warp = tid >> 5;
    const int grp  = lane >> 2;
    const int tq   = lane & 3;
    const int wr0  = warp * 16;
    const int rowsel = lane & 15;
    const int cb8    = (lane >> 4) * 8;

    const int m0 = blockIdx.y * 64;
    const int n0 = blockIdx.x * 64;

    float c[8][4];
    #pragma unroll
    for (int nt = 0; nt < 8; ++nt)
        #pragma unroll
        for (int i = 0; i < 4; ++i) c[nt][i] = 0.f;

    for (int kt = 0; kt < DM / 64; ++kt) {
        __syncthreads();
        const int k0 = kt * 64;
        #pragma unroll
        for (int j = tid; j < 64 * 8; j += 128) {
            int r = j >> 3, cc = (j & 7) * 8;
            size_t ga = (size_t)(m0 + r) * DM + k0 + cc;
            size_t gw = (size_t)(n0 + r) * DM + k0 + cc;
            *reinterpret_cast<uint4*>(sAh + r * STRB + cc) = *reinterpret_cast<const uint4*>(g_ah + ga);
            *reinterpret_cast<uint4*>(sAl + r * STRB + cc) = *reinterpret_cast<const uint4*>(g_al + ga);
            *reinterpret_cast<uint4*>(sWh + r * STRB + cc) = *reinterpret_cast<const uint4*>(g_wh + gw);
            *reinterpret_cast<uint4*>(sWl + r * STRB + cc) = *reinterpret_cast<const uint4*>(g_wl + gw);
        }
        __syncthreads();

        #pragma unroll
        for (int kb = 0; kb < 4; ++kb) {
            uint32_t ah[4], al[4];
            const int aoff = (wr0 + rowsel) * STRB + kb * 16 + cb8;
            ldsm4(ah, sAh + aoff);
            ldsm4(al, sAl + aoff);
            #pragma unroll
            for (int np = 0; np < 4; ++np) {
                uint32_t wh[4], wl[4];
                const int woff = (np * 16 + rowsel) * STRB + kb * 16 + cb8;
                ldsm4(wh, sWh + woff);
                ldsm4(wl, sWl + woff);
                mma16(c[2 * np],     ah, wh[0], wh[2]);
                mma16(c[2 * np],     ah, wl[0], wl[2]);
                mma16(c[2 * np],     al, wh[0], wh[2]);
                mma16(c[2 * np + 1], ah, wh[1], wh[3]);
                mma16(c[2 * np + 1], ah, wl[1], wl[3]);
                mma16(c[2 * np + 1], al, wh[1], wh[3]);
            }
        }
    }

    // Epilogue: bias + store fp32
    #pragma unroll
    for (int nt = 0; nt < 8; ++nt) {
        const int col = n0 + nt * 8 + tq * 2;
        const float b0 = bias[col], b1 = bias[col + 1];
        const size_t r0 = (size_t)(m0 + wr0 + grp) * DM + col;
        const size_t r1 = (size_t)(m0 + wr0 + grp + 8) * DM + col;
        out[r0]     = c[nt][0] + b0;
        out[r0 + 1] = c[nt][1] + b1;
        out[r1]     = c[nt][2] + b0;
        out[r1 + 1] = c[nt][3] + b1;
    }
}

// ---------------- launch ----------------

extern "C" void kernel_launch(void* const* d_in, const int* in_sizes, int n_in,
                              void* d_out, int out_size) {
    const float* values  = (const float*)d_in[0];
    const float* keys    = (const float*)d_in[1];
    const float* queries = (const float*)d_in[2];
    const float* fc_w    = (const float*)d_in[3];
    const float* fc_b    = (const float*)d_in[4];
    float* out = (float*)d_out;

    cudaFuncSetAttribute(attn_kernel, cudaFuncAttributeMaxDynamicSharedMemorySize, ATTN_SMEM);
    cudaFuncSetAttribute(fc_kernel, cudaFuncAttributeMaxDynamicSharedMemorySize, FC_SMEM);

    // Pre-split fp32 -> bf16 hi/lo (once per launch, elementwise)
    constexpr int QKV4 = NB * SL * DM / 4;   // 1,048,576 float4s
    constexpr int W4   = DM * DM / 4;        // 262,144 float4s
    split_q<<<QKV4 / 256, 256>>>((const float4*)queries);
    split_k<<<QKV4 / 256, 256>>>((const float4*)keys);
    split_v<<<QKV4 / 256, 256>>>((const float4*)values);
    split_w<<<W4 / 256, 256>>>((const float4*)fc_w);

    attn_kernel<<<dim3(SL / BM, NH, NB), 128, ATTN_SMEM>>>();
    fc_kernel<<<dim3(DM / 64, (NB * SL) / 64), 128, FC_SMEM>>>(fc_b, out);
}